// round 8
// baseline (speedup 1.0000x reference)
#include <cuda_runtime.h>
#include <cuda_bf16.h>
#include <cstdint>

// ---------------- problem constants ----------------
#define NROWS  10000
#define MPAD   10112           // 79 * 128
#define NHID   128
#define NFEAT  512
#define KPAD   10048           // 157 * 64 = 314 * 32
#define BKC    64
#define NCHUNK (KPAD / BKC)    // 157 (narrow kernel)
#define NCHUNK2 (KPAD / 32)    // 314 (wide kernel)
#define TILE_B  16384u         // narrow: 128 rows * 128B
#define STAGE_B (4u * TILE_B)  // 65536
#define NSTAGES 3
#define TC_SMEM (NSTAGES * STAGE_B)   // 196608
#define Z2 12                  // gemm2 K-split
#define Z4 6                   // gemm4 K-split (wide kernel)

// ---------------- scratch (__device__ globals; no allocs) ----------------
__device__ __align__(256) float g_T1[NROWS * NHID];
__device__ __align__(256) float g_H [NROWS * NHID];
__device__ __align__(256) float g_T2[NROWS * NFEAT];
__device__ __align__(256) float g_part[Z2 * (size_t)MPAD * NHID > Z4 * (size_t)MPAD * NFEAT
                                       ? Z2 * (size_t)MPAD * NHID
                                       : Z4 * (size_t)MPAD * NFEAT];
__device__ __align__(256) __nv_bfloat16 g_adj_hi[(size_t)MPAD * KPAD];
__device__ __align__(256) __nv_bfloat16 g_adj_lo[(size_t)MPAD * KPAD];
__device__ __align__(256) __nv_bfloat16 g_T1t_hi[NHID * KPAD];
__device__ __align__(256) __nv_bfloat16 g_T1t_lo[NHID * KPAD];
__device__ __align__(256) __nv_bfloat16 g_T2t_hi[NFEAT * KPAD];
__device__ __align__(256) __nv_bfloat16 g_T2t_lo[NFEAT * KPAD];

// ---------------- PTX helpers (legal on bare sm_103) ----------------
__device__ __forceinline__ uint32_t smem_u32(const void* p) {
    uint32_t a;
    asm("{ .reg .u64 t; cvta.to.shared.u64 t, %1; cvt.u32.u64 %0, t; }" : "=r"(a) : "l"(p));
    return a;
}
__device__ __forceinline__ uint32_t swz(uint32_t off) {
    return off ^ ((off >> 3) & 0x70);
}
__device__ __forceinline__ void cp_async16(uint32_t dst, const void* src) {
    asm volatile("cp.async.cg.shared.global [%0], [%1], 16;" :: "r"(dst), "l"(src));
}
__device__ __forceinline__ void cp_commit() {
    asm volatile("cp.async.commit_group;" ::: "memory");
}
template <int N>
__device__ __forceinline__ void cp_wait() {
    asm volatile("cp.async.wait_group %0;" :: "n"(N) : "memory");
}
__device__ __forceinline__ void ldsm4(uint32_t* r, uint32_t addr) {
    asm volatile("ldmatrix.sync.aligned.m8n8.x4.shared.b16 {%0,%1,%2,%3}, [%4];"
                 : "=r"(r[0]), "=r"(r[1]), "=r"(r[2]), "=r"(r[3]) : "r"(addr));
}
__device__ __forceinline__ void mma_bf16(float* d, const uint32_t* a,
                                         uint32_t b0, uint32_t b1) {
    asm volatile(
        "mma.sync.aligned.m16n8k16.row.col.f32.bf16.bf16.f32 "
        "{%0,%1,%2,%3}, {%4,%5,%6,%7}, {%8,%9}, {%0,%1,%2,%3};"
        : "+f"(d[0]), "+f"(d[1]), "+f"(d[2]), "+f"(d[3])
        : "r"(a[0]), "r"(a[1]), "r"(a[2]), "r"(a[3]), "r"(b0), "r"(b1));
}

// ============ narrow kernel: warp tile 32x32, CTA 128x128, BKC=64 (R7) ============
__global__ __launch_bounds__(512, 1)
void tc_gemm(const __nv_bfloat16* __restrict__ Ahi,
             const __nv_bfloat16* __restrict__ Alo,
             const __nv_bfloat16* __restrict__ Bhi,
             const __nv_bfloat16* __restrict__ Blo,
             float* __restrict__ C, int ldC, size_t part_stride)
{
    extern __shared__ __align__(128) char smem[];
    const uint32_t sbase = smem_u32(smem);
    const int tid  = threadIdx.x;
    const int wid  = tid >> 5;
    const int lane = tid & 31;
    const int wm = wid & 3;
    const int wn = wid >> 2;
    const int m0 = blockIdx.y * 128;
    const int n0 = blockIdx.x * 128;

    const int gz = gridDim.z, bz = blockIdx.z;
    const int cbeg = (NCHUNK * bz) / gz;
    const int cend = (NCHUNK * (bz + 1)) / gz;
    C += (size_t)bz * part_stride;

    const char* bases[4] = {
        (const char*)(Ahi + (size_t)m0 * KPAD),
        (const char*)(Alo + (size_t)m0 * KPAD),
        (const char*)(Bhi + (size_t)n0 * KPAD),
        (const char*)(Blo + (size_t)n0 * KPAD)
    };

    auto load_stage = [&](int c) {
        const uint32_t st = sbase + (uint32_t)(c % NSTAGES) * STAGE_B;
        const size_t kb = (size_t)c * (BKC * 2);
#pragma unroll
        for (int i = 0; i < 8; i++) {
            const int idx = tid + i * 512;
            const int t   = idx >> 10;
            const int rem = idx & 1023;
            const int r   = rem >> 3;
            const int cc  = rem & 7;
            cp_async16(st + (uint32_t)t * TILE_B + swz((uint32_t)(r * 128 + cc * 16)),
                       bases[t] + kb + (size_t)r * (KPAD * 2) + cc * 16);
        }
        cp_commit();
    };

    const uint32_t rL   = lane & 15;
    const uint32_t cAdd = lane >> 4;
    const uint32_t aRow0 = (uint32_t)(wm * 32 + rL);
    const uint32_t bRow0 = (uint32_t)(wn * 32 + rL);
    const uint32_t kOff0 = cAdd * 16u;

    float acc[2][4][4];
#pragma unroll
    for (int i = 0; i < 2; i++)
#pragma unroll
        for (int j = 0; j < 4; j++)
#pragma unroll
            for (int k = 0; k < 4; k++) acc[i][j][k] = 0.0f;

    load_stage(cbeg);
    if (cbeg + 1 < cend) load_stage(cbeg + 1);

    for (int c = cbeg; c < cend; c++) {
        if (c + 1 < cend) cp_wait<1>(); else cp_wait<0>();
        __syncthreads();
        if (c + 2 < cend) load_stage(c + 2);

        const uint32_t st   = sbase + (uint32_t)(c % NSTAGES) * STAGE_B;
        const uint32_t tAhi = st;
        const uint32_t tAlo = st + TILE_B;
        const uint32_t tBhi = st + 2u * TILE_B;
        const uint32_t tBlo = st + 3u * TILE_B;

#pragma unroll
        for (int ks = 0; ks < 4; ks++) {
            const uint32_t kb = kOff0 + (uint32_t)ks * 32u;
            uint32_t Ah[2][4], Al[2][4], Bh[2][4], Bl[2][4];
#pragma unroll
            for (int mt = 0; mt < 2; mt++) {
                const uint32_t off = (aRow0 + mt * 16u) * 128u + kb;
                ldsm4(Ah[mt], tAhi + swz(off));
                ldsm4(Al[mt], tAlo + swz(off));
            }
#pragma unroll
            for (int nh = 0; nh < 2; nh++) {
                const uint32_t off = (bRow0 + nh * 16u) * 128u + kb;
                ldsm4(Bh[nh], tBhi + swz(off));
                ldsm4(Bl[nh], tBlo + swz(off));
            }
#pragma unroll
            for (int mt = 0; mt < 2; mt++) {
                mma_bf16(acc[mt][0], Ah[mt], Bh[0][0], Bh[0][2]);
                mma_bf16(acc[mt][1], Ah[mt], Bh[0][1], Bh[0][3]);
                mma_bf16(acc[mt][2], Ah[mt], Bh[1][0], Bh[1][2]);
                mma_bf16(acc[mt][3], Ah[mt], Bh[1][1], Bh[1][3]);
                mma_bf16(acc[mt][0], Ah[mt], Bl[0][0], Bl[0][2]);
                mma_bf16(acc[mt][1], Ah[mt], Bl[0][1], Bl[0][3]);
                mma_bf16(acc[mt][2], Ah[mt], Bl[1][0], Bl[1][2]);
                mma_bf16(acc[mt][3], Ah[mt], Bl[1][1], Bl[1][3]);
                mma_bf16(acc[mt][0], Al[mt], Bh[0][0], Bh[0][2]);
                mma_bf16(acc[mt][1], Al[mt], Bh[0][1], Bh[0][3]);
                mma_bf16(acc[mt][2], Al[mt], Bh[1][0], Bh[1][2]);
                mma_bf16(acc[mt][3], Al[mt], Bh[1][1], Bh[1][3]);
            }
        }
    }

    const int trow  = lane >> 2;
    const int tcol2 = (lane & 3) * 2;
#pragma unroll
    for (int mt = 0; mt < 2; mt++) {
#pragma unroll
        for (int h = 0; h < 2; h++) {
            const int gr = m0 + wm * 32 + mt * 16 + h * 8 + trow;
#pragma unroll
            for (int nf = 0; nf < 4; nf++) {
                const int gc = n0 + wn * 32 + nf * 8 + tcol2;
                float2 v;
                v.x = acc[mt][nf][h * 2 + 0];
                v.y = acc[mt][nf][h * 2 + 1];
                *reinterpret_cast<float2*>(&C[(size_t)gr * ldC + gc]) = v;
            }
        }
    }
}

// ============ wide kernel: warp tile 32x64, CTA 128x256, BKC=32 ============
// Smem layout: two 64B tile-rows packed per 128B smem row, swz128.
// addr(row, g) = (row>>1)*128 + (row&1)*64 + g*16 -> swz (conflict-free ldsm).
#define W_BM 128
#define W_BN 256
#define W_ATB ((uint32_t)W_BM * 64u)    // 8192
#define W_BTB ((uint32_t)W_BN * 64u)    // 16384
#define W_STAGE (2u * W_ATB + 2u * W_BTB)  // 49152
#define W_SMEM (3u * W_STAGE)              // 147456

__device__ __forceinline__ uint32_t w_addr(uint32_t row, uint32_t g) {
    return swz(((row >> 1) * 128u) + ((row & 1) * 64u) + g * 16u);
}

__global__ __launch_bounds__(512, 1)
void tc_gemm_w(const __nv_bfloat16* __restrict__ Ahi,
               const __nv_bfloat16* __restrict__ Alo,
               const __nv_bfloat16* __restrict__ Bhi,
               const __nv_bfloat16* __restrict__ Blo,
               float* __restrict__ C, int ldC, size_t part_stride)
{
    extern __shared__ __align__(128) char smem[];
    const uint32_t sbase = smem_u32(smem);
    const int tid  = threadIdx.x;
    const int wid  = tid >> 5;
    const int lane = tid & 31;
    const int wm = wid & 3;            // 4 warp-rows of 32
    const int wn = wid >> 2;           // 4 warp-cols of 64
    const int m0 = blockIdx.y * W_BM;
    const int n0 = blockIdx.x * W_BN;

    const int gz = gridDim.z, bz = blockIdx.z;
    const int cbeg = (NCHUNK2 * bz) / gz;
    const int cend = (NCHUNK2 * (bz + 1)) / gz;
    C += (size_t)bz * part_stride;

    const char* baseAhi = (const char*)(Ahi + (size_t)m0 * KPAD);
    const char* baseAlo = (const char*)(Alo + (size_t)m0 * KPAD);
    const char* baseBhi = (const char*)(Bhi + (size_t)n0 * KPAD);
    const char* baseBlo = (const char*)(Blo + (size_t)n0 * KPAD);

    auto load_stage = [&](int c) {
        const uint32_t st = sbase + (uint32_t)(c % 3) * W_STAGE;
        const size_t kb = (size_t)c * 64;   // 32 k * 2B
#pragma unroll
        for (int i = 0; i < 6; i++) {
            const int idx = tid + i * 512;     // 0..3071 granules
            const int row = idx >> 2;          // 0..767
            const int g   = idx & 3;
            const char* src;
            uint32_t tb;
            uint32_t r;
            if (row < W_BM)               { r = row;               src = baseAhi; tb = 0; }
            else if (row < 2 * W_BM)      { r = row - W_BM;        src = baseAlo; tb = W_ATB; }
            else if (row < 2*W_BM + W_BN) { r = row - 2 * W_BM;    src = baseBhi; tb = 2u * W_ATB; }
            else                          { r = row - 2*W_BM - W_BN; src = baseBlo; tb = 2u * W_ATB + W_BTB; }
            cp_async16(st + tb + w_addr(r, (uint32_t)g),
                       src + (size_t)r * (KPAD * 2) + kb + g * 16);
        }
        cp_commit();
    };

    const uint32_t rL   = lane & 15;
    const uint32_t cAdd = lane >> 4;
    const uint32_t aRow0 = (uint32_t)(wm * 32) + rL;
    const uint32_t bRow0 = (uint32_t)(wn * 64) + rL;

    float acc[2][8][4];
#pragma unroll
    for (int i = 0; i < 2; i++)
#pragma unroll
        for (int j = 0; j < 8; j++)
#pragma unroll
            for (int k = 0; k < 4; k++) acc[i][j][k] = 0.0f;

    load_stage(cbeg);
    if (cbeg + 1 < cend) load_stage(cbeg + 1);

    for (int c = cbeg; c < cend; c++) {
        if (c + 1 < cend) cp_wait<1>(); else cp_wait<0>();
        __syncthreads();
        if (c + 2 < cend) load_stage(c + 2);

        const uint32_t st   = sbase + (uint32_t)(c % 3) * W_STAGE;
        const uint32_t tAhi = st;
        const uint32_t tAlo = st + W_ATB;
        const uint32_t tBhi = st + 2u * W_ATB;
        const uint32_t tBlo = tBhi + W_BTB;

#pragma unroll
        for (int ks = 0; ks < 2; ks++) {
            const uint32_t g = (uint32_t)(ks * 2) + cAdd;
            uint32_t Ah[2][4], Al[2][4];
#pragma unroll
            for (int mt = 0; mt < 2; mt++) {
                const uint32_t off = w_addr(aRow0 + mt * 16u, g);
                ldsm4(Ah[mt], tAhi + off);
                ldsm4(Al[mt], tAlo + off);
            }
#pragma unroll
            for (int nh = 0; nh < 4; nh++) {
                const uint32_t off = w_addr(bRow0 + nh * 16u, g);
                uint32_t Bh[4], Bl[4];
                ldsm4(Bh, tBhi + off);
                ldsm4(Bl, tBlo + off);
#pragma unroll
                for (int mt = 0; mt < 2; mt++) {
                    float* a0 = acc[mt][2 * nh + 0];
                    float* a1 = acc[mt][2 * nh + 1];
                    mma_bf16(a0, Ah[mt], Bh[0], Bh[2]);   // hi*hi
                    mma_bf16(a1, Ah[mt], Bh[1], Bh[3]);
                    mma_bf16(a0, Ah[mt], Bl[0], Bl[2]);   // hi*lo
                    mma_bf16(a1, Ah[mt], Bl[1], Bl[3]);
                    mma_bf16(a0, Al[mt], Bh[0], Bh[2]);   // lo*hi
                    mma_bf16(a1, Al[mt], Bh[1], Bh[3]);
                }
            }
        }
    }

    const int trow  = lane >> 2;
    const int tcol2 = (lane & 3) * 2;
#pragma unroll
    for (int mt = 0; mt < 2; mt++) {
#pragma unroll
        for (int h = 0; h < 2; h++) {
            const int gr = m0 + wm * 32 + mt * 16 + h * 8 + trow;
#pragma unroll
            for (int nf = 0; nf < 8; nf++) {
                const int gc = n0 + wn * 64 + nf * 8 + tcol2;
                float2 v;
                v.x = acc[mt][nf][h * 2 + 0];
                v.y = acc[mt][nf][h * 2 + 1];
                *reinterpret_cast<float2*>(&C[(size_t)gr * ldC + gc]) = v;
            }
        }
    }
}

// ---------------- split-K reduce: out = (sum parts) + bias (, relu) ----------------
template <int NP, bool RELU>
__global__ void reduce_kernel(const float* __restrict__ part, size_t stride,
                              const float* __restrict__ bias,
                              float* __restrict__ out, int rows, int cols)
{
    const int t = blockIdx.x * blockDim.x + threadIdx.x;
    if (t >= rows * (cols / 4)) return;
    const int r = t / (cols / 4);
    const int c = (t % (cols / 4)) * 4;
    float4 s = *reinterpret_cast<const float4*>(bias + c);
#pragma unroll
    for (int p = 0; p < NP; p++) {
        const float4 v = *reinterpret_cast<const float4*>(part + p * stride + (size_t)r * cols + c);
        s.x += v.x; s.y += v.y; s.z += v.z; s.w += v.w;
    }
    if (RELU) {
        s.x = fmaxf(s.x, 0.0f); s.y = fmaxf(s.y, 0.0f);
        s.z = fmaxf(s.z, 0.0f); s.w = fmaxf(s.w, 0.0f);
    }
    *reinterpret_cast<float4*>(out + (size_t)r * cols + c) = s;
}

// ---------------- adj split: fp32 -> bf16 hi/lo [MPAD,KPAD] ----------------
__global__ void split_adj_kernel(const float* __restrict__ adj,
                                 __nv_bfloat16* __restrict__ hi,
                                 __nv_bfloat16* __restrict__ lo)
{
    const long long t = (long long)blockIdx.x * blockDim.x + threadIdx.x;
    const long long total = (long long)MPAD * (KPAD / 4);
    if (t >= total) return;
    const int c4 = (int)(t % (KPAD / 4));
    const int r  = (int)(t / (KPAD / 4));
    const int k  = c4 * 4;
    float4 v = make_float4(0.f, 0.f, 0.f, 0.f);
    if (r < NROWS && k < NROWS)
        v = *reinterpret_cast<const float4*>(adj + (size_t)r * NROWS + k);
    __nv_bfloat16 h0 = __float2bfloat16(v.x), h1 = __float2bfloat16(v.y);
    __nv_bfloat16 h2 = __float2bfloat16(v.z), h3 = __float2bfloat16(v.w);
    __nv_bfloat16 l0 = __float2bfloat16(v.x - __bfloat162float(h0));
    __nv_bfloat16 l1 = __float2bfloat16(v.y - __bfloat162float(h1));
    __nv_bfloat16 l2 = __float2bfloat16(v.z - __bfloat162float(h2));
    __nv_bfloat16 l3 = __float2bfloat16(v.w - __bfloat162float(h3));
    __nv_bfloat162 H01, H23, L01, L23;
    H01.x = h0; H01.y = h1; H23.x = h2; H23.y = h3;
    L01.x = l0; L01.y = l1; L23.x = l2; L23.y = l3;
    __nv_bfloat162* hp = reinterpret_cast<__nv_bfloat162*>(hi + (size_t)r * KPAD + k);
    __nv_bfloat162* lp = reinterpret_cast<__nv_bfloat162*>(lo + (size_t)r * KPAD + k);
    hp[0] = H01; hp[1] = H23;
    lp[0] = L01; lp[1] = L23;
}

// -------- tiled transpose + split: fp32 [R,C] -> bf16 hi/lo [C, KPAD] --------
__global__ void tsplit_kernel(const float* __restrict__ in, int R, int C,
                              __nv_bfloat16* __restrict__ hi,
                              __nv_bfloat16* __restrict__ lo)
{
    __shared__ float tile[32][33];
    const int tx = threadIdx.x, ty = threadIdx.y;
    const int c0 = blockIdx.x * 32;
    const int k0 = blockIdx.y * 32;
#pragma unroll
    for (int i = 0; i < 4; i++) {
        const int k = k0 + ty + i * 8;
        tile[ty + i * 8][tx] = (k < R) ? in[(size_t)k * C + (c0 + tx)] : 0.0f;
    }
    __syncthreads();
#pragma unroll
    for (int i = 0; i < 4; i++) {
        const int c = c0 + ty + i * 8;
        const float v = tile[tx][ty + i * 8];
        const __nv_bfloat16 h = __float2bfloat16(v);
        hi[(size_t)c * KPAD + k0 + tx] = h;
        lo[(size_t)c * KPAD + k0 + tx] = __float2bfloat16(v - __bfloat162float(h));
    }
}

// ---------------- SIMT SGEMM (small GEMMs) ----------------
template <int BM, int BN, int BK, int TM, int TN>
__global__ __launch_bounds__(256)
void sgemm_kernel(int M, int N, int K,
                  const float* __restrict__ A,
                  const float* __restrict__ B,
                  float* __restrict__ C)
{
    __shared__ float As[BK][BM];
    __shared__ float Bs[BK][BN];
    constexpr int TCOLS = BN / TN;
    const int tid  = threadIdx.x;
    const int tCol = tid % TCOLS;
    const int tRow = tid / TCOLS;
    const int rowBase = blockIdx.y * BM;
    const int colBase = blockIdx.x * BN;

    float acc[TM][TN];
#pragma unroll
    for (int i = 0; i < TM; i++)
#pragma unroll
        for (int j = 0; j < TN; j++) acc[i][j] = 0.0f;

    for (int k0 = 0; k0 < K; k0 += BK) {
#pragma unroll
        for (int i = tid; i < BM * BK; i += 256) {
            const int r = i / BK, c = i % BK;
            const int gr = rowBase + r;
            As[c][r] = (gr < M) ? A[(size_t)gr * K + (k0 + c)] : 0.0f;
        }
#pragma unroll
        for (int i = tid; i < BK * BN; i += 256) {
            const int r = i / BN, c = i % BN;
            Bs[r][c] = B[(size_t)(k0 + r) * N + (colBase + c)];
        }
        __syncthreads();
#pragma unroll
        for (int kk = 0; kk < BK; kk++) {
            float regA[TM], regB[TN];
            const float4* a4 = reinterpret_cast<const float4*>(&As[kk][tRow * TM]);
#pragma unroll
            for (int i = 0; i < TM / 4; i++) {
                float4 v = a4[i];
                regA[4*i+0] = v.x; regA[4*i+1] = v.y; regA[4*i+2] = v.z; regA[4*i+3] = v.w;
            }
            const float4* b4 = reinterpret_cast<const float4*>(&Bs[kk][tCol * TN]);
#pragma unroll
            for (int j = 0; j < TN / 4; j++) {
                float4 v = b4[j];
                regB[4*j+0] = v.x; regB[4*j+1] = v.y; regB[4*j+2] = v.z; regB[4*j+3] = v.w;
            }
#pragma unroll
            for (int i = 0; i < TM; i++)
#pragma unroll
                for (int j = 0; j < TN; j++)
                    acc[i][j] = fmaf(regA[i], regB[j], acc[i][j]);
        }
        __syncthreads();
    }
#pragma unroll
    for (int i = 0; i < TM; i++) {
        const int gr = rowBase + tRow * TM + i;
        if (gr < M) {
#pragma unroll
            for (int j = 0; j < TN; j += 4) {
                const int gc = colBase + tCol * TN + j;
                float4 v;
                v.x = acc[i][j+0]; v.y = acc[i][j+1]; v.z = acc[i][j+2]; v.w = acc[i][j+3];
                *reinterpret_cast<float4*>(&C[(size_t)gr * N + gc]) = v;
            }
        }
    }
}

// ---------------- launcher ----------------
extern "C" void kernel_launch(void* const* d_in, const int* in_sizes, int n_in,
                              void* d_out, int out_size)
{
    const float* x   = (const float*)d_in[0];
    const float* adj = (const float*)d_in[1];
    const float* W1  = (const float*)d_in[2];
    const float* b1  = (const float*)d_in[3];
    const float* W2  = (const float*)d_in[4];
    const float* b2  = (const float*)d_in[5];
    float* out = (float*)d_out;

    float *T1, *H, *T2, *part;
    __nv_bfloat16 *Ahi, *Alo, *T1hi, *T1lo, *T2hi, *T2lo;
    cudaGetSymbolAddress((void**)&T1,  g_T1);
    cudaGetSymbolAddress((void**)&H,   g_H);
    cudaGetSymbolAddress((void**)&T2,  g_T2);
    cudaGetSymbolAddress((void**)&part, g_part);
    cudaGetSymbolAddress((void**)&Ahi, g_adj_hi);
    cudaGetSymbolAddress((void**)&Alo, g_adj_lo);
    cudaGetSymbolAddress((void**)&T1hi, g_T1t_hi);
    cudaGetSymbolAddress((void**)&T1lo, g_T1t_lo);
    cudaGetSymbolAddress((void**)&T2hi, g_T2t_hi);
    cudaGetSymbolAddress((void**)&T2lo, g_T2t_lo);

    cudaFuncSetAttribute(tc_gemm,   cudaFuncAttributeMaxDynamicSharedMemorySize, TC_SMEM);
    cudaFuncSetAttribute(tc_gemm_w, cudaFuncAttributeMaxDynamicSharedMemorySize, W_SMEM);

    // adj -> bf16 hi/lo (padded)
    {
        const long long total = (long long)MPAD * (KPAD / 4);
        split_adj_kernel<<<(unsigned)((total + 255) / 256), 256>>>(adj, Ahi, Alo);
    }
    // T1 = x @ W1
    sgemm_kernel<64, 128, 8, 4, 8><<<dim3(1, (NROWS + 63) / 64), 256>>>(
        NROWS, NHID, NFEAT, x, W1, T1);
    // T1t split -> [NHID, KPAD]
    tsplit_kernel<<<dim3(NHID / 32, KPAD / 32), dim3(32, 8)>>>(T1, NROWS, NHID, T1hi, T1lo);
    // gemm2 partials (narrow kernel, K-split Z2)
    tc_gemm<<<dim3(1, MPAD / 128, Z2), 512, TC_SMEM>>>(
        Ahi, Alo, T1hi, T1lo, part, NHID, (size_t)MPAD * NHID);
    // H = relu(sum parts + b1)
    reduce_kernel<Z2, true><<<(NROWS * (NHID / 4) + 255) / 256, 256>>>(
        part, (size_t)MPAD * NHID, b1, H, NROWS, NHID);
    // T2 = H @ W2
    sgemm_kernel<128, 128, 8, 8, 8><<<dim3(NFEAT / 128, (NROWS + 127) / 128), 256>>>(
        NROWS, NFEAT, NHID, H, W2, T2);
    // T2t split -> [NFEAT, KPAD]
    tsplit_kernel<<<dim3(NFEAT / 32, KPAD / 32), dim3(32, 8)>>>(T2, NROWS, NFEAT, T2hi, T2lo);
    // gemm4 partials (wide kernel 128x256, K-split Z4)
    tc_gemm_w<<<dim3(NFEAT / 256, MPAD / 128, Z4), 512, W_SMEM>>>(
        Ahi, Alo, T2hi, T2lo, part, NFEAT, (size_t)MPAD * NFEAT);
    // out = sum parts + b2
    reduce_kernel<Z4, false><<<(NROWS * (NFEAT / 4) + 255) / 256, 256>>>(
        part, (size_t)MPAD * NFEAT, b2, out, NROWS, NFEAT);
}

// round 9
// speedup vs baseline: 1.3272x; 1.3272x over previous
#include <cuda_runtime.h>
#include <cuda_fp16.h>
#include <cstdint>

// ---------------- problem constants ----------------
#define NROWS  10000
#define MPAD   10112           // 79 * 128
#define NHID   128
#define NFEAT  512
#define KPAD   10048           // 157 * 64
#define BKC    64
#define NCHUNK (KPAD / BKC)    // 157
#define TILE_B  16384u         // 128 rows * 128B (swizzled)
#define STAGE_B (3u * TILE_B)  // 49152 (Ah, Al, Bh)
#define NSTAGES 3
#define TC_SMEM (NSTAGES * STAGE_B)   // 147456
#define Z2 12                  // gemm2 K-split
#define Z4 4                   // gemm4 K-split

// ---------------- scratch (__device__ globals; no allocs) ----------------
__device__ __align__(256) float g_T1[NROWS * NHID];
__device__ __align__(256) float g_H [NROWS * NHID];
__device__ __align__(256) float g_T2[NROWS * NFEAT];
__device__ __align__(256) float g_part[Z2 * (size_t)MPAD * NHID > Z4 * (size_t)MPAD * NFEAT
                                       ? Z2 * (size_t)MPAD * NHID
                                       : Z4 * (size_t)MPAD * NFEAT];
__device__ __align__(256) __half g_adj_hi[(size_t)MPAD * KPAD];
__device__ __align__(256) __half g_adj_lo[(size_t)MPAD * KPAD];
__device__ __align__(256) __half g_T1t[NHID * KPAD];
__device__ __align__(256) __half g_T2t[NFEAT * KPAD];

// ---------------- PTX helpers (legal on bare sm_103) ----------------
__device__ __forceinline__ uint32_t smem_u32(const void* p) {
    uint32_t a;
    asm("{ .reg .u64 t; cvta.to.shared.u64 t, %1; cvt.u32.u64 %0, t; }" : "=r"(a) : "l"(p));
    return a;
}
__device__ __forceinline__ uint32_t swz(uint32_t off) {
    return off ^ ((off >> 3) & 0x70);
}
__device__ __forceinline__ void cp_async16(uint32_t dst, const void* src) {
    asm volatile("cp.async.cg.shared.global [%0], [%1], 16;" :: "r"(dst), "l"(src));
}
__device__ __forceinline__ void cp_commit() {
    asm volatile("cp.async.commit_group;" ::: "memory");
}
template <int N>
__device__ __forceinline__ void cp_wait() {
    asm volatile("cp.async.wait_group %0;" :: "n"(N) : "memory");
}
__device__ __forceinline__ void ldsm4(uint32_t* r, uint32_t addr) {
    asm volatile("ldmatrix.sync.aligned.m8n8.x4.shared.b16 {%0,%1,%2,%3}, [%4];"
                 : "=r"(r[0]), "=r"(r[1]), "=r"(r[2]), "=r"(r[3]) : "r"(addr));
}
__device__ __forceinline__ void mma_f16(float* d, const uint32_t* a,
                                        uint32_t b0, uint32_t b1) {
    asm volatile(
        "mma.sync.aligned.m16n8k16.row.col.f32.f16.f16.f32 "
        "{%0,%1,%2,%3}, {%4,%5,%6,%7}, {%8,%9}, {%0,%1,%2,%3};"
        : "+f"(d[0]), "+f"(d[1]), "+f"(d[2]), "+f"(d[3])
        : "r"(a[0]), "r"(a[1]), "r"(a[2]), "r"(a[3]), "r"(b0), "r"(b1));
}

// ---------------- HMMA fp16-split GEMM (partial sums) ----------------
// part[z][m][n] = sum_{k in range z} (Ah+Al)[m][k] * Bh[n][k]   (2 products)
// A: [MPAD, KPAD] fp16-split K-major; B: [Ntot, KPAD] fp16 K-major (= round16(B^T)).
__global__ __launch_bounds__(512, 1)
void tc_gemm(const __half* __restrict__ Ahi,
             const __half* __restrict__ Alo,
             const __half* __restrict__ Bhi,
             float* __restrict__ C, int ldC, size_t part_stride)
{
    extern __shared__ __align__(128) char smem[];
    const uint32_t sbase = smem_u32(smem);
    const int tid  = threadIdx.x;
    const int wid  = tid >> 5;
    const int lane = tid & 31;
    const int wm = wid & 3;            // 4 warp-rows of 32
    const int wn = wid >> 2;           // 4 warp-cols of 32
    const int m0 = blockIdx.y * 128;
    const int n0 = blockIdx.x * 128;

    const int gz = gridDim.z, bz = blockIdx.z;
    const int cbeg = (NCHUNK * bz) / gz;
    const int cend = (NCHUNK * (bz + 1)) / gz;
    C += (size_t)bz * part_stride;

    const char* bases[3] = {
        (const char*)(Ahi + (size_t)m0 * KPAD),
        (const char*)(Alo + (size_t)m0 * KPAD),
        (const char*)(Bhi + (size_t)n0 * KPAD)
    };

    auto load_stage = [&](int c) {
        const uint32_t st = sbase + (uint32_t)(c % NSTAGES) * STAGE_B;
        const size_t kb = (size_t)c * (BKC * 2);
#pragma unroll
        for (int i = 0; i < 6; i++) {
            const int idx = tid + i * 512;          // 0..3071
            const int t   = idx >> 10;              // tile 0..2
            const int rem = idx & 1023;
            const int r   = rem >> 3;               // row 0..127
            const int cc  = rem & 7;                // 16B chunk
            cp_async16(st + (uint32_t)t * TILE_B + swz((uint32_t)(r * 128 + cc * 16)),
                       bases[t] + kb + (size_t)r * (KPAD * 2) + cc * 16);
        }
        cp_commit();
    };

    // ldmatrix logical offsets (swizzle applied per-use)
    const uint32_t rL   = lane & 15;
    const uint32_t cAdd = lane >> 4;
    const uint32_t aRow0 = (uint32_t)(wm * 32 + rL);
    const uint32_t bRow0 = (uint32_t)(wn * 32 + rL);
    const uint32_t kOff0 = cAdd * 16u;

    float acc[2][4][4];
#pragma unroll
    for (int i = 0; i < 2; i++)
#pragma unroll
        for (int j = 0; j < 4; j++)
#pragma unroll
            for (int k = 0; k < 4; k++) acc[i][j][k] = 0.0f;

    // prologue
    load_stage(cbeg);
    if (cbeg + 1 < cend) load_stage(cbeg + 1);

    for (int c = cbeg; c < cend; c++) {
        if (c + 1 < cend) cp_wait<1>(); else cp_wait<0>();
        __syncthreads();
        if (c + 2 < cend) load_stage(c + 2);   // overlaps with compute below

        const uint32_t st   = sbase + (uint32_t)(c % NSTAGES) * STAGE_B;
        const uint32_t tAhi = st;
        const uint32_t tAlo = st + TILE_B;
        const uint32_t tBhi = st + 2u * TILE_B;

#pragma unroll
        for (int ks = 0; ks < 4; ks++) {
            const uint32_t kb = kOff0 + (uint32_t)ks * 32u;
            uint32_t Ah[2][4], Al[2][4], Bh[2][4];
#pragma unroll
            for (int mt = 0; mt < 2; mt++) {
                const uint32_t off = (aRow0 + mt * 16u) * 128u + kb;
                ldsm4(Ah[mt], tAhi + swz(off));
                ldsm4(Al[mt], tAlo + swz(off));
            }
#pragma unroll
            for (int nh = 0; nh < 2; nh++) {
                const uint32_t off = (bRow0 + nh * 16u) * 128u + kb;
                ldsm4(Bh[nh], tBhi + swz(off));
            }
#pragma unroll
            for (int mt = 0; mt < 2; mt++) {
                // hi product
                mma_f16(acc[mt][0], Ah[mt], Bh[0][0], Bh[0][2]);
                mma_f16(acc[mt][1], Ah[mt], Bh[0][1], Bh[0][3]);
                mma_f16(acc[mt][2], Ah[mt], Bh[1][0], Bh[1][2]);
                mma_f16(acc[mt][3], Ah[mt], Bh[1][1], Bh[1][3]);
                // lo product
                mma_f16(acc[mt][0], Al[mt], Bh[0][0], Bh[0][2]);
                mma_f16(acc[mt][1], Al[mt], Bh[0][1], Bh[0][3]);
                mma_f16(acc[mt][2], Al[mt], Bh[1][0], Bh[1][2]);
                mma_f16(acc[mt][3], Al[mt], Bh[1][1], Bh[1][3]);
            }
        }
    }

    // ---- epilogue: raw partial sums ----
    const int trow  = lane >> 2;
    const int tcol2 = (lane & 3) * 2;
#pragma unroll
    for (int mt = 0; mt < 2; mt++) {
#pragma unroll
        for (int h = 0; h < 2; h++) {
            const int gr = m0 + wm * 32 + mt * 16 + h * 8 + trow;
#pragma unroll
            for (int nf = 0; nf < 4; nf++) {
                const int gc = n0 + wn * 32 + nf * 8 + tcol2;
                float2 v;
                v.x = acc[mt][nf][h * 2 + 0];
                v.y = acc[mt][nf][h * 2 + 1];
                *reinterpret_cast<float2*>(&C[(size_t)gr * ldC + gc]) = v;
            }
        }
    }
}

// ---------------- split-K reduce: out = (sum parts) + bias (, relu) ----------------
template <int NP, bool RELU>
__global__ void reduce_kernel(const float* __restrict__ part, size_t stride,
                              const float* __restrict__ bias,
                              float* __restrict__ out, int rows, int cols)
{
    const int t = blockIdx.x * blockDim.x + threadIdx.x;
    if (t >= rows * (cols / 4)) return;
    const int r = t / (cols / 4);
    const int c = (t % (cols / 4)) * 4;
    float4 s = *reinterpret_cast<const float4*>(bias + c);
#pragma unroll
    for (int p = 0; p < NP; p++) {
        const float4 v = *reinterpret_cast<const float4*>(part + p * stride + (size_t)r * cols + c);
        s.x += v.x; s.y += v.y; s.z += v.z; s.w += v.w;
    }
    if (RELU) {
        s.x = fmaxf(s.x, 0.0f); s.y = fmaxf(s.y, 0.0f);
        s.z = fmaxf(s.z, 0.0f); s.w = fmaxf(s.w, 0.0f);
    }
    *reinterpret_cast<float4*>(out + (size_t)r * cols + c) = s;
}

// ---------------- adj split: fp32 -> fp16 hi/lo [MPAD,KPAD] ----------------
__global__ void split_adj_kernel(const float* __restrict__ adj,
                                 __half* __restrict__ hi,
                                 __half* __restrict__ lo)
{
    const long long t = (long long)blockIdx.x * blockDim.x + threadIdx.x;
    const long long total = (long long)MPAD * (KPAD / 4);
    if (t >= total) return;
    const int c4 = (int)(t % (KPAD / 4));
    const int r  = (int)(t / (KPAD / 4));
    const int k  = c4 * 4;
    float4 v = make_float4(0.f, 0.f, 0.f, 0.f);
    if (r < NROWS && k < NROWS)
        v = *reinterpret_cast<const float4*>(adj + (size_t)r * NROWS + k);
    __half h0 = __float2half(v.x), h1 = __float2half(v.y);
    __half h2 = __float2half(v.z), h3 = __float2half(v.w);
    __half l0 = __float2half(v.x - __half2float(h0));
    __half l1 = __float2half(v.y - __half2float(h1));
    __half l2 = __float2half(v.z - __half2float(h2));
    __half l3 = __float2half(v.w - __half2float(h3));
    __half2 H01, H23, L01, L23;
    H01.x = h0; H01.y = h1; H23.x = h2; H23.y = h3;
    L01.x = l0; L01.y = l1; L23.x = l2; L23.y = l3;
    __half2* hp = reinterpret_cast<__half2*>(hi + (size_t)r * KPAD + k);
    __half2* lp = reinterpret_cast<__half2*>(lo + (size_t)r * KPAD + k);
    hp[0] = H01; hp[1] = H23;
    lp[0] = L01; lp[1] = L23;
}

// -------- tiled transpose + round: fp32 [R,C] -> fp16 [C, KPAD] --------
// grid (C/32, KPAD/32), block (32, 8). Coalesced on both sides.
__global__ void tsplit_kernel(const float* __restrict__ in, int R, int C,
                              __half* __restrict__ hi)
{
    __shared__ float tile[32][33];
    const int tx = threadIdx.x, ty = threadIdx.y;
    const int c0 = blockIdx.x * 32;
    const int k0 = blockIdx.y * 32;
#pragma unroll
    for (int i = 0; i < 4; i++) {
        const int k = k0 + ty + i * 8;
        tile[ty + i * 8][tx] = (k < R) ? in[(size_t)k * C + (c0 + tx)] : 0.0f;
    }
    __syncthreads();
#pragma unroll
    for (int i = 0; i < 4; i++) {
        const int c = c0 + ty + i * 8;
        hi[(size_t)c * KPAD + k0 + tx] = __float2half(tile[tx][ty + i * 8]);
    }
}

// ---------------- SIMT SGEMM (small GEMMs) ----------------
template <int BM, int BN, int BK, int TM, int TN>
__global__ __launch_bounds__(256)
void sgemm_kernel(int M, int N, int K,
                  const float* __restrict__ A,
                  const float* __restrict__ B,
                  float* __restrict__ C)
{
    __shared__ float As[BK][BM];
    __shared__ float Bs[BK][BN];
    constexpr int TCOLS = BN / TN;
    const int tid  = threadIdx.x;
    const int tCol = tid % TCOLS;
    const int tRow = tid / TCOLS;
    const int rowBase = blockIdx.y * BM;
    const int colBase = blockIdx.x * BN;

    float acc[TM][TN];
#pragma unroll
    for (int i = 0; i < TM; i++)
#pragma unroll
        for (int j = 0; j < TN; j++) acc[i][j] = 0.0f;

    for (int k0 = 0; k0 < K; k0 += BK) {
#pragma unroll
        for (int i = tid; i < BM * BK; i += 256) {
            const int r = i / BK, c = i % BK;
            const int gr = rowBase + r;
            As[c][r] = (gr < M) ? A[(size_t)gr * K + (k0 + c)] : 0.0f;
        }
#pragma unroll
        for (int i = tid; i < BK * BN; i += 256) {
            const int r = i / BN, c = i % BN;
            Bs[r][c] = B[(size_t)(k0 + r) * N + (colBase + c)];
        }
        __syncthreads();
#pragma unroll
        for (int kk = 0; kk < BK; kk++) {
            float regA[TM], regB[TN];
            const float4* a4 = reinterpret_cast<const float4*>(&As[kk][tRow * TM]);
#pragma unroll
            for (int i = 0; i < TM / 4; i++) {
                float4 v = a4[i];
                regA[4*i+0] = v.x; regA[4*i+1] = v.y; regA[4*i+2] = v.z; regA[4*i+3] = v.w;
            }
            const float4* b4 = reinterpret_cast<const float4*>(&Bs[kk][tCol * TN]);
#pragma unroll
            for (int j = 0; j < TN / 4; j++) {
                float4 v = b4[j];
                regB[4*j+0] = v.x; regB[4*j+1] = v.y; regB[4*j+2] = v.z; regB[4*j+3] = v.w;
            }
#pragma unroll
            for (int i = 0; i < TM; i++)
#pragma unroll
                for (int j = 0; j < TN; j++)
                    acc[i][j] = fmaf(regA[i], regB[j], acc[i][j]);
        }
        __syncthreads();
    }
#pragma unroll
    for (int i = 0; i < TM; i++) {
        const int gr = rowBase + tRow * TM + i;
        if (gr < M) {
#pragma unroll
            for (int j = 0; j < TN; j += 4) {
                const int gc = colBase + tCol * TN + j;
                float4 v;
                v.x = acc[i][j+0]; v.y = acc[i][j+1]; v.z = acc[i][j+2]; v.w = acc[i][j+3];
                *reinterpret_cast<float4*>(&C[(size_t)gr * N + gc]) = v;
            }
        }
    }
}

// ---------------- launcher ----------------
extern "C" void kernel_launch(void* const* d_in, const int* in_sizes, int n_in,
                              void* d_out, int out_size)
{
    const float* x   = (const float*)d_in[0];
    const float* adj = (const float*)d_in[1];
    const float* W1  = (const float*)d_in[2];
    const float* b1  = (const float*)d_in[3];
    const float* W2  = (const float*)d_in[4];
    const float* b2  = (const float*)d_in[5];
    float* out = (float*)d_out;

    float *T1, *H, *T2, *part;
    __half *Ahi, *Alo, *T1t, *T2t;
    cudaGetSymbolAddress((void**)&T1,  g_T1);
    cudaGetSymbolAddress((void**)&H,   g_H);
    cudaGetSymbolAddress((void**)&T2,  g_T2);
    cudaGetSymbolAddress((void**)&part, g_part);
    cudaGetSymbolAddress((void**)&Ahi, g_adj_hi);
    cudaGetSymbolAddress((void**)&Alo, g_adj_lo);
    cudaGetSymbolAddress((void**)&T1t, g_T1t);
    cudaGetSymbolAddress((void**)&T2t, g_T2t);

    cudaFuncSetAttribute(tc_gemm, cudaFuncAttributeMaxDynamicSharedMemorySize, TC_SMEM);

    // adj -> fp16 hi/lo (padded)
    {
        const long long total = (long long)MPAD * (KPAD / 4);
        split_adj_kernel<<<(unsigned)((total + 255) / 256), 256>>>(adj, Ahi, Alo);
    }
    // T1 = x @ W1
    sgemm_kernel<64, 128, 8, 4, 8><<<dim3(1, (NROWS + 63) / 64), 256>>>(
        NROWS, NHID, NFEAT, x, W1, T1);
    // T1t -> [NHID, KPAD] fp16 (coalesced tiled transpose + round)
    tsplit_kernel<<<dim3(NHID / 32, KPAD / 32), dim3(32, 8)>>>(T1, NROWS, NHID, T1t);
    // gemm2 partials (K-split Z2)
    tc_gemm<<<dim3(1, MPAD / 128, Z2), 512, TC_SMEM>>>(
        Ahi, Alo, T1t, part, NHID, (size_t)MPAD * NHID);
    // H = relu(sum parts + b1)
    reduce_kernel<Z2, true><<<(NROWS * (NHID / 4) + 255) / 256, 256>>>(
        part, (size_t)MPAD * NHID, b1, H, NROWS, NHID);
    // T2 = H @ W2
    sgemm_kernel<128, 128, 8, 8, 8><<<dim3(NFEAT / 128, (NROWS + 127) / 128), 256>>>(
        NROWS, NFEAT, NHID, H, W2, T2);
    // T2t -> [NFEAT, KPAD] fp16
    tsplit_kernel<<<dim3(NFEAT / 32, KPAD / 32), dim3(32, 8)>>>(T2, NROWS, NFEAT, T2t);
    // gemm4 partials (K-split Z4)
    tc_gemm<<<dim3(NFEAT / 128, MPAD / 128, Z4), 512, TC_SMEM>>>(
        Ahi, Alo, T2t, part, NFEAT, (size_t)MPAD * NFEAT);
    // out = sum parts + b2
    reduce_kernel<Z4, false><<<(NROWS * (NFEAT / 4) + 255) / 256, 256>>>(
        part, (size_t)MPAD * NFEAT, b2, out, NROWS, NFEAT);
}

// round 10
// speedup vs baseline: 1.4316x; 1.0786x over previous
#include <cuda_runtime.h>
#include <cuda_fp16.h>
#include <cstdint>

// ---------------- problem constants ----------------
#define NROWS  10000
#define MPAD   10112           // 79 * 128
#define NHID   128
#define NFEAT  512
#define KPAD   10112           // == MPAD, 158 * 64
#define BKC    64
#define NCHUNK (KPAD / BKC)    // 158
#define TILE_B  16384u         // 128 rows * 128B (swizzled)
#define STAGE_B (3u * TILE_B)  // 49152 (Ah, Al, Bh)
#define NSTAGES 3
#define TC_SMEM (NSTAGES * STAGE_B)   // 147456
#define Z2 12                  // gemm2 K-split
#define Z4 6                   // gemm4 K-split

// ---------------- scratch (__device__ globals; no allocs) ----------------
__device__ __align__(256) float g_T1[NROWS * NHID];
__device__ __align__(256) float g_part[Z2 * (size_t)MPAD * NHID > Z4 * (size_t)MPAD * NFEAT
                                       ? Z2 * (size_t)MPAD * NHID
                                       : Z4 * (size_t)MPAD * NFEAT];
__device__ __align__(256) __half g_adj_hi[(size_t)MPAD * KPAD];
__device__ __align__(256) __half g_adj_lo[(size_t)MPAD * KPAD];
__device__ __align__(256) __half g_T1t[NHID * KPAD];      // [NHID, KPAD]
__device__ __align__(256) __half g_Hh [(size_t)MPAD * NHID];  // H fp16 [MPAD, NHID]
__device__ __align__(256) __half g_W2t_hi[NFEAT * NHID];  // W2^T hi [NFEAT, NHID]
__device__ __align__(256) __half g_W2t_lo[NFEAT * NHID];
__device__ __align__(256) __half g_T2t[(size_t)NFEAT * KPAD];  // T2^T fp16 [NFEAT, KPAD]

// ---------------- PTX helpers (legal on bare sm_103) ----------------
__device__ __forceinline__ uint32_t smem_u32(const void* p) {
    uint32_t a;
    asm("{ .reg .u64 t; cvta.to.shared.u64 t, %1; cvt.u32.u64 %0, t; }" : "=r"(a) : "l"(p));
    return a;
}
__device__ __forceinline__ uint32_t swz(uint32_t off) {
    return off ^ ((off >> 3) & 0x70);
}
__device__ __forceinline__ void cp_async16(uint32_t dst, const void* src) {
    asm volatile("cp.async.cg.shared.global [%0], [%1], 16;" :: "r"(dst), "l"(src));
}
__device__ __forceinline__ void cp_commit() {
    asm volatile("cp.async.commit_group;" ::: "memory");
}
template <int N>
__device__ __forceinline__ void cp_wait() {
    asm volatile("cp.async.wait_group %0;" :: "n"(N) : "memory");
}
__device__ __forceinline__ void ldsm4(uint32_t* r, uint32_t addr) {
    asm volatile("ldmatrix.sync.aligned.m8n8.x4.shared.b16 {%0,%1,%2,%3}, [%4];"
                 : "=r"(r[0]), "=r"(r[1]), "=r"(r[2]), "=r"(r[3]) : "r"(addr));
}
__device__ __forceinline__ void mma_f16(float* d, const uint32_t* a,
                                        uint32_t b0, uint32_t b1) {
    asm volatile(
        "mma.sync.aligned.m16n8k16.row.col.f32.f16.f16.f32 "
        "{%0,%1,%2,%3}, {%4,%5,%6,%7}, {%8,%9}, {%0,%1,%2,%3};"
        : "+f"(d[0]), "+f"(d[1]), "+f"(d[2]), "+f"(d[3])
        : "r"(a[0]), "r"(a[1]), "r"(a[2]), "r"(a[3]), "r"(b0), "r"(b1));
}

// ============ narrow kernel: warp tile 32x32, CTA 128x128, BKC=64 ============
// C[m][n] (+= over z ranges) = sum_k (Ah+Al)[m][k] * Bh[n][k]   (fp16 split, 2 products)
// OutT = float (raw partials) or __half (rounded output, gz==1).
template <typename OutT>
__global__ __launch_bounds__(512, 1)
void tc_gemm(const __half* __restrict__ Ahi,
             const __half* __restrict__ Alo,
             const __half* __restrict__ Bhi,
             OutT* __restrict__ C,
             int ldA, int ldB, int ldC, int nchunk, size_t part_stride)
{
    extern __shared__ __align__(128) char smem[];
    const uint32_t sbase = smem_u32(smem);
    const int tid  = threadIdx.x;
    const int wid  = tid >> 5;
    const int lane = tid & 31;
    const int wm = wid & 3;
    const int wn = wid >> 2;
    const int m0 = blockIdx.y * 128;
    const int n0 = blockIdx.x * 128;

    const int gz = gridDim.z, bz = blockIdx.z;
    const int cbeg = (nchunk * bz) / gz;
    const int cend = (nchunk * (bz + 1)) / gz;
    C += (size_t)bz * part_stride;

    const char* bases[3] = {
        (const char*)(Ahi + (size_t)m0 * ldA),
        (const char*)(Alo + (size_t)m0 * ldA),
        (const char*)(Bhi + (size_t)n0 * ldB)
    };
    const size_t strides[3] = { (size_t)ldA * 2, (size_t)ldA * 2, (size_t)ldB * 2 };

    auto load_stage = [&](int c) {
        const uint32_t st = sbase + (uint32_t)(c % NSTAGES) * STAGE_B;
        const size_t kb = (size_t)c * (BKC * 2);
#pragma unroll
        for (int i = 0; i < 6; i++) {
            const int idx = tid + i * 512;          // 0..3071
            const int t   = idx >> 10;              // tile 0..2
            const int rem = idx & 1023;
            const int r   = rem >> 3;               // row 0..127
            const int cc  = rem & 7;                // 16B chunk
            cp_async16(st + (uint32_t)t * TILE_B + swz((uint32_t)(r * 128 + cc * 16)),
                       bases[t] + kb + (size_t)r * strides[t] + cc * 16);
        }
        cp_commit();
    };

    const uint32_t rL   = lane & 15;
    const uint32_t cAdd = lane >> 4;
    const uint32_t aRow0 = (uint32_t)(wm * 32 + rL);
    const uint32_t bRow0 = (uint32_t)(wn * 32 + rL);
    const uint32_t kOff0 = cAdd * 16u;

    float acc[2][4][4];
#pragma unroll
    for (int i = 0; i < 2; i++)
#pragma unroll
        for (int j = 0; j < 4; j++)
#pragma unroll
            for (int k = 0; k < 4; k++) acc[i][j][k] = 0.0f;

    load_stage(cbeg);
    if (cbeg + 1 < cend) load_stage(cbeg + 1);

    for (int c = cbeg; c < cend; c++) {
        if (c + 1 < cend) cp_wait<1>(); else cp_wait<0>();
        __syncthreads();
        if (c + 2 < cend) load_stage(c + 2);

        const uint32_t st   = sbase + (uint32_t)(c % NSTAGES) * STAGE_B;
        const uint32_t tAhi = st;
        const uint32_t tAlo = st + TILE_B;
        const uint32_t tBhi = st + 2u * TILE_B;

#pragma unroll
        for (int ks = 0; ks < 4; ks++) {
            const uint32_t kb = kOff0 + (uint32_t)ks * 32u;
            uint32_t Ah[2][4], Al[2][4], Bh[2][4];
#pragma unroll
            for (int mt = 0; mt < 2; mt++) {
                const uint32_t off = (aRow0 + mt * 16u) * 128u + kb;
                ldsm4(Ah[mt], tAhi + swz(off));
                ldsm4(Al[mt], tAlo + swz(off));
            }
#pragma unroll
            for (int nh = 0; nh < 2; nh++) {
                const uint32_t off = (bRow0 + nh * 16u) * 128u + kb;
                ldsm4(Bh[nh], tBhi + swz(off));
            }
#pragma unroll
            for (int mt = 0; mt < 2; mt++) {
                mma_f16(acc[mt][0], Ah[mt], Bh[0][0], Bh[0][2]);
                mma_f16(acc[mt][1], Ah[mt], Bh[0][1], Bh[0][3]);
                mma_f16(acc[mt][2], Ah[mt], Bh[1][0], Bh[1][2]);
                mma_f16(acc[mt][3], Ah[mt], Bh[1][1], Bh[1][3]);
                mma_f16(acc[mt][0], Al[mt], Bh[0][0], Bh[0][2]);
                mma_f16(acc[mt][1], Al[mt], Bh[0][1], Bh[0][3]);
                mma_f16(acc[mt][2], Al[mt], Bh[1][0], Bh[1][2]);
                mma_f16(acc[mt][3], Al[mt], Bh[1][1], Bh[1][3]);
            }
        }
    }

    // ---- epilogue ----
    const int trow  = lane >> 2;
    const int tcol2 = (lane & 3) * 2;
#pragma unroll
    for (int mt = 0; mt < 2; mt++) {
#pragma unroll
        for (int h = 0; h < 2; h++) {
            const int gr = m0 + wm * 32 + mt * 16 + h * 8 + trow;
#pragma unroll
            for (int nf = 0; nf < 4; nf++) {
                const int gc = n0 + wn * 32 + nf * 8 + tcol2;
                if constexpr (sizeof(OutT) == 2) {
                    __half2 v;
                    v.x = __float2half(acc[mt][nf][h * 2 + 0]);
                    v.y = __float2half(acc[mt][nf][h * 2 + 1]);
                    *reinterpret_cast<__half2*>(
                        reinterpret_cast<__half*>(C) + (size_t)gr * ldC + gc) = v;
                } else {
                    float2 v;
                    v.x = acc[mt][nf][h * 2 + 0];
                    v.y = acc[mt][nf][h * 2 + 1];
                    *reinterpret_cast<float2*>(
                        reinterpret_cast<float*>(C) + (size_t)gr * ldC + gc) = v;
                }
            }
        }
    }
}

// ============ wide kernel: warp tile 32x64, CTA 128x256, BKC=64 ============
#define W_ATB 16384u                    // 128 rows * 128B
#define W_BTB 32768u                    // 256 rows * 128B
#define W_STAGE (2u * W_ATB + W_BTB)    // 65536
#define W_SMEM (3u * W_STAGE)           // 196608

__global__ __launch_bounds__(512, 1)
void tc_gemm_w(const __half* __restrict__ Ahi,
               const __half* __restrict__ Alo,
               const __half* __restrict__ Bhi,
               float* __restrict__ C, int ldC, size_t part_stride)
{
    extern __shared__ __align__(128) char smem[];
    const uint32_t sbase = smem_u32(smem);
    const int tid  = threadIdx.x;
    const int wid  = tid >> 5;
    const int lane = tid & 31;
    const int wm = wid & 3;            // 4 warp-rows of 32
    const int wn = wid >> 2;           // 4 warp-cols of 64
    const int m0 = blockIdx.y * 128;
    const int n0 = blockIdx.x * 256;

    const int gz = gridDim.z, bz = blockIdx.z;
    const int cbeg = (NCHUNK * bz) / gz;
    const int cend = (NCHUNK * (bz + 1)) / gz;
    C += (size_t)bz * part_stride;

    const char* baseAhi = (const char*)(Ahi + (size_t)m0 * KPAD);
    const char* baseAlo = (const char*)(Alo + (size_t)m0 * KPAD);
    const char* baseBhi = (const char*)(Bhi + (size_t)n0 * KPAD);

    auto load_stage = [&](int c) {
        const uint32_t st = sbase + (uint32_t)(c % 3) * W_STAGE;
        const size_t kb = (size_t)c * (BKC * 2);
#pragma unroll
        for (int i = 0; i < 8; i++) {
            const int idx = tid + i * 512;          // 0..4095
            const char* src;
            uint32_t dst;
            if (idx < 2048) {                       // Ah / Al: 128 rows each
                const int t   = idx >> 10;
                const int rem = idx & 1023;
                const int r   = rem >> 3;
                const int cc  = rem & 7;
                src = (t == 0 ? baseAhi : baseAlo) + kb + (size_t)r * (KPAD * 2) + cc * 16;
                dst = st + (uint32_t)t * W_ATB + swz((uint32_t)(r * 128 + cc * 16));
            } else {                                // Bh: 256 rows
                const int rem = idx - 2048;
                const int r   = rem >> 3;
                const int cc  = rem & 7;
                src = baseBhi + kb + (size_t)r * (KPAD * 2) + cc * 16;
                dst = st + 2u * W_ATB + swz((uint32_t)(r * 128 + cc * 16));
            }
            cp_async16(dst, src);
        }
        cp_commit();
    };

    const uint32_t rL   = lane & 15;
    const uint32_t cAdd = lane >> 4;
    const uint32_t aRow0 = (uint32_t)(wm * 32) + rL;
    const uint32_t bRow0 = (uint32_t)(wn * 64) + rL;
    const uint32_t kOff0 = cAdd * 16u;

    float acc[2][8][4];
#pragma unroll
    for (int i = 0; i < 2; i++)
#pragma unroll
        for (int j = 0; j < 8; j++)
#pragma unroll
            for (int k = 0; k < 4; k++) acc[i][j][k] = 0.0f;

    load_stage(cbeg);
    if (cbeg + 1 < cend) load_stage(cbeg + 1);

    for (int c = cbeg; c < cend; c++) {
        if (c + 1 < cend) cp_wait<1>(); else cp_wait<0>();
        __syncthreads();
        if (c + 2 < cend) load_stage(c + 2);

        const uint32_t st   = sbase + (uint32_t)(c % 3) * W_STAGE;
        const uint32_t tAhi = st;
        const uint32_t tAlo = st + W_ATB;
        const uint32_t tBhi = st + 2u * W_ATB;

#pragma unroll
        for (int ks = 0; ks < 4; ks++) {
            const uint32_t kb = kOff0 + (uint32_t)ks * 32u;
            uint32_t Ah[2][4], Al[2][4];
#pragma unroll
            for (int mt = 0; mt < 2; mt++) {
                const uint32_t off = (aRow0 + mt * 16u) * 128u + kb;
                ldsm4(Ah[mt], tAhi + swz(off));
                ldsm4(Al[mt], tAlo + swz(off));
            }
#pragma unroll
            for (int nh = 0; nh < 4; nh++) {
                const uint32_t off = (bRow0 + nh * 16u) * 128u + kb;
                uint32_t Bh[4];
                ldsm4(Bh, tBhi + swz(off));
#pragma unroll
                for (int mt = 0; mt < 2; mt++) {
                    float* a0 = acc[mt][2 * nh + 0];
                    float* a1 = acc[mt][2 * nh + 1];
                    mma_f16(a0, Ah[mt], Bh[0], Bh[2]);
                    mma_f16(a1, Ah[mt], Bh[1], Bh[3]);
                    mma_f16(a0, Al[mt], Bh[0], Bh[2]);
                    mma_f16(a1, Al[mt], Bh[1], Bh[3]);
                }
            }
        }
    }

    const int trow  = lane >> 2;
    const int tcol2 = (lane & 3) * 2;
#pragma unroll
    for (int mt = 0; mt < 2; mt++) {
#pragma unroll
        for (int h = 0; h < 2; h++) {
            const int gr = m0 + wm * 32 + mt * 16 + h * 8 + trow;
#pragma unroll
            for (int nf = 0; nf < 8; nf++) {
                const int gc = n0 + wn * 64 + nf * 8 + tcol2;
                float2 v;
                v.x = acc[mt][nf][h * 2 + 0];
                v.y = acc[mt][nf][h * 2 + 1];
                *reinterpret_cast<float2*>(&C[(size_t)gr * ldC + gc]) = v;
            }
        }
    }
}

// ------- reduce for H: Hh = half(relu(sum parts + b1)), rows = MPAD -------
template <int NP>
__global__ void reduce_h_kernel(const float* __restrict__ part, size_t stride,
                                const float* __restrict__ bias,
                                __half* __restrict__ out)
{
    const int t = blockIdx.x * blockDim.x + threadIdx.x;
    if (t >= MPAD * (NHID / 4)) return;
    const int r = t / (NHID / 4);
    const int c = (t % (NHID / 4)) * 4;
    float4 s = *reinterpret_cast<const float4*>(bias + c);
#pragma unroll
    for (int p = 0; p < NP; p++) {
        const float4 v = *reinterpret_cast<const float4*>(part + p * stride + (size_t)r * NHID + c);
        s.x += v.x; s.y += v.y; s.z += v.z; s.w += v.w;
    }
    __half2 h0, h1;
    h0.x = __float2half(fmaxf(s.x, 0.0f));
    h0.y = __float2half(fmaxf(s.y, 0.0f));
    h1.x = __float2half(fmaxf(s.z, 0.0f));
    h1.y = __float2half(fmaxf(s.w, 0.0f));
    __half2* op = reinterpret_cast<__half2*>(out + (size_t)r * NHID + c);
    op[0] = h0; op[1] = h1;
}

// ------- reduce for out: out = sum parts + bias (fp32) -------
template <int NP>
__global__ void reduce_kernel(const float* __restrict__ part, size_t stride,
                              const float* __restrict__ bias,
                              float* __restrict__ out, int rows, int cols)
{
    const int t = blockIdx.x * blockDim.x + threadIdx.x;
    if (t >= rows * (cols / 4)) return;
    const int r = t / (cols / 4);
    const int c = (t % (cols / 4)) * 4;
    float4 s = *reinterpret_cast<const float4*>(bias + c);
#pragma unroll
    for (int p = 0; p < NP; p++) {
        const float4 v = *reinterpret_cast<const float4*>(part + p * stride + (size_t)r * cols + c);
        s.x += v.x; s.y += v.y; s.z += v.z; s.w += v.w;
    }
    *reinterpret_cast<float4*>(out + (size_t)r * cols + c) = s;
}

// ---------------- adj split: fp32 -> fp16 hi/lo [MPAD,KPAD] ----------------
__global__ void split_adj_kernel(const float* __restrict__ adj,
                                 __half* __restrict__ hi,
                                 __half* __restrict__ lo)
{
    const long long t = (long long)blockIdx.x * blockDim.x + threadIdx.x;
    const long long total = (long long)MPAD * (KPAD / 4);
    if (t >= total) return;
    const int c4 = (int)(t % (KPAD / 4));
    const int r  = (int)(t / (KPAD / 4));
    const int k  = c4 * 4;
    float4 v = make_float4(0.f, 0.f, 0.f, 0.f);
    if (r < NROWS && k + 3 < NROWS)
        v = *reinterpret_cast<const float4*>(adj + (size_t)r * NROWS + k);
    else if (r < NROWS && k < NROWS) {
        v.x = adj[(size_t)r * NROWS + k];
        if (k + 1 < NROWS) v.y = adj[(size_t)r * NROWS + k + 1];
        if (k + 2 < NROWS) v.z = adj[(size_t)r * NROWS + k + 2];
    }
    __half h0 = __float2half(v.x), h1 = __float2half(v.y);
    __half h2 = __float2half(v.z), h3 = __float2half(v.w);
    __half l0 = __float2half(v.x - __half2float(h0));
    __half l1 = __float2half(v.y - __half2float(h1));
    __half l2 = __float2half(v.z - __half2float(h2));
    __half l3 = __float2half(v.w - __half2float(h3));
    __half2 H01, H23, L01, L23;
    H01.x = h0; H01.y = h1; H23.x = h2; H23.y = h3;
    L01.x = l0; L01.y = l1; L23.x = l2; L23.y = l3;
    __half2* hp = reinterpret_cast<__half2*>(hi + (size_t)r * KPAD + k);
    __half2* lp = reinterpret_cast<__half2*>(lo + (size_t)r * KPAD + k);
    hp[0] = H01; hp[1] = H23;
    lp[0] = L01; lp[1] = L23;
}

// -------- tiled transpose + round: fp32 [R,C] -> fp16 [C, KPAD] --------
__global__ void tsplit_round_kernel(const float* __restrict__ in, int R, int C,
                                    __half* __restrict__ hi)
{
    __shared__ float tile[32][33];
    const int tx = threadIdx.x, ty = threadIdx.y;
    const int c0 = blockIdx.x * 32;
    const int k0 = blockIdx.y * 32;
#pragma unroll
    for (int i = 0; i < 4; i++) {
        const int k = k0 + ty + i * 8;
        tile[ty + i * 8][tx] = (k < R) ? in[(size_t)k * C + (c0 + tx)] : 0.0f;
    }
    __syncthreads();
#pragma unroll
    for (int i = 0; i < 4; i++) {
        const int c = c0 + ty + i * 8;
        hi[(size_t)c * KPAD + k0 + tx] = __float2half(tile[tx][ty + i * 8]);
    }
}

// -------- W2 transpose + split: fp32 [NHID, NFEAT] -> fp16 hi/lo [NFEAT, NHID] --------
__global__ void w2t_split_kernel(const float* __restrict__ W2,
                                 __half* __restrict__ hi,
                                 __half* __restrict__ lo)
{
    __shared__ float tile[32][33];
    const int tx = threadIdx.x, ty = threadIdx.y;
    const int c0 = blockIdx.x * 32;   // NFEAT dim
    const int k0 = blockIdx.y * 32;   // NHID dim
#pragma unroll
    for (int i = 0; i < 4; i++) {
        const int k = k0 + ty + i * 8;
        tile[ty + i * 8][tx] = W2[(size_t)k * NFEAT + (c0 + tx)];
    }
    __syncthreads();
#pragma unroll
    for (int i = 0; i < 4; i++) {
        const int c = c0 + ty + i * 8;
        const float v = tile[tx][ty + i * 8];
        const __half h = __float2half(v);
        hi[(size_t)c * NHID + k0 + tx] = h;
        lo[(size_t)c * NHID + k0 + tx] = __float2half(v - __half2float(h));
    }
}

// ---------------- SIMT SGEMM (T1 = x @ W1) ----------------
template <int BM, int BN, int BK, int TM, int TN>
__global__ __launch_bounds__(256)
void sgemm_kernel(int M, int N, int K,
                  const float* __restrict__ A,
                  const float* __restrict__ B,
                  float* __restrict__ C)
{
    __shared__ float As[BK][BM];
    __shared__ float Bs[BK][BN];
    constexpr int TCOLS = BN / TN;
    const int tid  = threadIdx.x;
    const int tCol = tid % TCOLS;
    const int tRow = tid / TCOLS;
    const int rowBase = blockIdx.y * BM;
    const int colBase = blockIdx.x * BN;

    float acc[TM][TN];
#pragma unroll
    for (int i = 0; i < TM; i++)
#pragma unroll
        for (int j = 0; j < TN; j++) acc[i][j] = 0.0f;

    for (int k0 = 0; k0 < K; k0 += BK) {
#pragma unroll
        for (int i = tid; i < BM * BK; i += 256) {
            const int r = i / BK, c = i % BK;
            const int gr = rowBase + r;
            As[c][r] = (gr < M) ? A[(size_t)gr * K + (k0 + c)] : 0.0f;
        }
#pragma unroll
        for (int i = tid; i < BK * BN; i += 256) {
            const int r = i / BN, c = i % BN;
            Bs[r][c] = B[(size_t)(k0 + r) * N + (colBase + c)];
        }
        __syncthreads();
#pragma unroll
        for (int kk = 0; kk < BK; kk++) {
            float regA[TM], regB[TN];
            const float4* a4 = reinterpret_cast<const float4*>(&As[kk][tRow * TM]);
#pragma unroll
            for (int i = 0; i < TM / 4; i++) {
                float4 v = a4[i];
                regA[4*i+0] = v.x; regA[4*i+1] = v.y; regA[4*i+2] = v.z; regA[4*i+3] = v.w;
            }
            const float4* b4 = reinterpret_cast<const float4*>(&Bs[kk][tCol * TN]);
#pragma unroll
            for (int j = 0; j < TN / 4; j++) {
                float4 v = b4[j];
                regB[4*j+0] = v.x; regB[4*j+1] = v.y; regB[4*j+2] = v.z; regB[4*j+3] = v.w;
            }
#pragma unroll
            for (int i = 0; i < TM; i++)
#pragma unroll
                for (int j = 0; j < TN; j++)
                    acc[i][j] = fmaf(regA[i], regB[j], acc[i][j]);
        }
        __syncthreads();
    }
#pragma unroll
    for (int i = 0; i < TM; i++) {
        const int gr = rowBase + tRow * TM + i;
        if (gr < M) {
#pragma unroll
            for (int j = 0; j < TN; j += 4) {
                const int gc = colBase + tCol * TN + j;
                float4 v;
                v.x = acc[i][j+0]; v.y = acc[i][j+1]; v.z = acc[i][j+2]; v.w = acc[i][j+3];
                *reinterpret_cast<float4*>(&C[(size_t)gr * N + gc]) = v;
            }
        }
    }
}

// ---------------- launcher ----------------
extern "C" void kernel_launch(void* const* d_in, const int* in_sizes, int n_in,
                              void* d_out, int out_size)
{
    const float* x   = (const float*)d_in[0];
    const float* adj = (const float*)d_in[1];
    const float* W1  = (const float*)d_in[2];
    const float* b1  = (const float*)d_in[3];
    const float* W2  = (const float*)d_in[4];
    const float* b2  = (const float*)d_in[5];
    float* out = (float*)d_out;

    float *T1, *part;
    __half *Ahi, *Alo, *T1t, *Hh, *W2thi, *W2tlo, *T2t;
    cudaGetSymbolAddress((void**)&T1,   g_T1);
    cudaGetSymbolAddress((void**)&part, g_part);
    cudaGetSymbolAddress((void**)&Ahi,  g_adj_hi);
    cudaGetSymbolAddress((void**)&Alo,  g_adj_lo);
    cudaGetSymbolAddress((void**)&T1t,  g_T1t);
    cudaGetSymbolAddress((void**)&Hh,   g_Hh);
    cudaGetSymbolAddress((void**)&W2thi, g_W2t_hi);
    cudaGetSymbolAddress((void**)&W2tlo, g_W2t_lo);
    cudaGetSymbolAddress((void**)&T2t,  g_T2t);

    cudaFuncSetAttribute(tc_gemm<float>,  cudaFuncAttributeMaxDynamicSharedMemorySize, TC_SMEM);
    cudaFuncSetAttribute(tc_gemm<__half>, cudaFuncAttributeMaxDynamicSharedMemorySize, TC_SMEM);
    cudaFuncSetAttribute(tc_gemm_w,       cudaFuncAttributeMaxDynamicSharedMemorySize, W_SMEM);

    // adj -> fp16 hi/lo (padded to MPAD x KPAD)
    {
        const long long total = (long long)MPAD * (KPAD / 4);
        split_adj_kernel<<<(unsigned)((total + 255) / 256), 256>>>(adj, Ahi, Alo);
    }
    // T1 = x @ W1   (SIMT fp32)
    sgemm_kernel<64, 128, 8, 4, 8><<<dim3(1, (NROWS + 63) / 64), 256>>>(
        NROWS, NHID, NFEAT, x, W1, T1);
    // T1t = round16(T1^T) [NHID, KPAD]
    tsplit_round_kernel<<<dim3(NHID / 32, KPAD / 32), dim3(32, 8)>>>(T1, NROWS, NHID, T1t);
    // gemm2 partials: part[z] = adj_split @ T1t^T
    tc_gemm<float><<<dim3(1, MPAD / 128, Z2), 512, TC_SMEM>>>(
        Ahi, Alo, T1t, part, KPAD, KPAD, NHID, NCHUNK, (size_t)MPAD * NHID);
    // Hh = half(relu(sum parts + b1))  [MPAD, NHID]
    reduce_h_kernel<Z2><<<(MPAD * (NHID / 4) + 255) / 256, 256>>>(
        part, (size_t)MPAD * NHID, b1, Hh);
    // W2t hi/lo  [NFEAT, NHID]
    w2t_split_kernel<<<dim3(NFEAT / 32, NHID / 32), dim3(32, 8)>>>(W2, W2thi, W2tlo);
    // T2t = half((W2t_hi+W2t_lo) @ Hh^T)  [NFEAT, KPAD], K = NHID (2 chunks)
    tc_gemm<__half><<<dim3(MPAD / 128, NFEAT / 128, 1), 512, TC_SMEM>>>(
        W2thi, W2tlo, Hh, T2t, NHID, NHID, KPAD, NHID / BKC, 0);
    // gemm4 partials (wide 128x256): part[z] = adj_split @ T2t^T
    tc_gemm_w<<<dim3(NFEAT / 256, MPAD / 128, Z4), 512, W_SMEM>>>(
        Ahi, Alo, T2t, part, NFEAT, (size_t)MPAD * NFEAT);
    // out = sum parts + b2
    reduce_kernel<Z4><<<(NROWS * (NFEAT / 4) + 255) / 256, 256>>>(
        part, (size_t)MPAD * NFEAT, b2, out, NROWS, NFEAT);
}

// round 11
// speedup vs baseline: 2.5631x; 1.7904x over previous
#include <cuda_runtime.h>
#include <cuda_fp16.h>
#include <cstdint>

// ---------------- problem constants ----------------
#define NROWS  10000
#define MPAD   10240           // 80*128, 40*256
#define NHID   128
#define NFEAT  512
#define KPAD   10112           // 158*64, 79*128
#define BKC    64
#define NCHUNK (KPAD / BKC)    // 158
#define Z2 11                  // gemm2 K-split
#define Z4 6                   // gemm4 K-split
#define TC_SMEM 147456         // 3 stages x 48KB (all variants)

// ---------------- scratch (__device__ globals; no allocs) ----------------
__device__ __align__(256) float g_part[(size_t)Z4 * MPAD * NFEAT];   // >= Z2*MPAD*NHID
__device__ __align__(256) __half g_adj_h[(size_t)MPAD * KPAD];       // round16(adj), padded
__device__ __align__(256) __half g_xh[(size_t)KPAD * NFEAT];         // round16(x), padded rows
__device__ __align__(256) __half g_W1t_hi[NHID * NFEAT];             // W1^T hi [NHID, NFEAT]
__device__ __align__(256) __half g_W1t_lo[NHID * NFEAT];
__device__ __align__(256) __half g_T1t[(size_t)NHID * KPAD];         // [NHID, KPAD]
__device__ __align__(256) __half g_Hh [(size_t)MPAD * NHID];         // H fp16 [MPAD, NHID]
__device__ __align__(256) __half g_W2t_hi[NFEAT * NHID];             // W2^T hi [NFEAT, NHID]
__device__ __align__(256) __half g_W2t_lo[NFEAT * NHID];
__device__ __align__(256) __half g_T2t[(size_t)NFEAT * KPAD];        // T2^T fp16 [NFEAT, KPAD]

// ---------------- PTX helpers (legal on bare sm_103) ----------------
__device__ __forceinline__ uint32_t smem_u32(const void* p) {
    uint32_t a;
    asm("{ .reg .u64 t; cvta.to.shared.u64 t, %1; cvt.u32.u64 %0, t; }" : "=r"(a) : "l"(p));
    return a;
}
__device__ __forceinline__ uint32_t swz(uint32_t off) {
    return off ^ ((off >> 3) & 0x70);
}
__device__ __forceinline__ void cp_async16(uint32_t dst, const void* src) {
    asm volatile("cp.async.cg.shared.global [%0], [%1], 16;" :: "r"(dst), "l"(src));
}
__device__ __forceinline__ void cp_commit() {
    asm volatile("cp.async.commit_group;" ::: "memory");
}
template <int N>
__device__ __forceinline__ void cp_wait() {
    asm volatile("cp.async.wait_group %0;" :: "n"(N) : "memory");
}
__device__ __forceinline__ void ldsm4(uint32_t* r, uint32_t addr) {
    asm volatile("ldmatrix.sync.aligned.m8n8.x4.shared.b16 {%0,%1,%2,%3}, [%4];"
                 : "=r"(r[0]), "=r"(r[1]), "=r"(r[2]), "=r"(r[3]) : "r"(addr));
}
__device__ __forceinline__ void mma_f16(float* d, const uint32_t* a,
                                        uint32_t b0, uint32_t b1) {
    asm volatile(
        "mma.sync.aligned.m16n8k16.row.col.f32.f16.f16.f32 "
        "{%0,%1,%2,%3}, {%4,%5,%6,%7}, {%8,%9}, {%0,%1,%2,%3};"
        : "+f"(d[0]), "+f"(d[1]), "+f"(d[2]), "+f"(d[3])
        : "r"(a[0]), "r"(a[1]), "r"(a[2]), "r"(a[3]), "r"(b0), "r"(b1));
}

// ---------------- unified HMMA fp16 GEMM ----------------
// C[m][n] = sum_k A[m][k]*B[n][k]  (+ A_lo product if DUAL); K-major A, B.
// CTA tile AM x BN; 16 warps (4x4); warp tile (AM/4) x (BN/4).
// gridDim.z = K-split count; partial z written at C + z*part_stride (OutT float).
template <int AM, int BN, bool DUAL, typename OutT>
__global__ __launch_bounds__(512, 1)
void tc_gemm(const __half* __restrict__ Ahi,
             const __half* __restrict__ Alo,
             const __half* __restrict__ Bhi,
             OutT* __restrict__ C,
             int ldA, int ldB, int ldC, int nchunk, size_t part_stride)
{
    constexpr int MT = AM / 64;                 // A 16-row frags per warp
    constexpr int NH = BN / 64;                 // B ldsm per warp (16-row units)
    constexpr uint32_t A_B = (uint32_t)AM * 128u;
    constexpr uint32_t B_B = (uint32_t)BN * 128u;
    constexpr uint32_t SS  = (DUAL ? 2u : 1u) * A_B + B_B;   // 48KB all configs
    constexpr int AG = AM * 8;                  // granules per A tile
    constexpr int NG = (DUAL ? 2 : 1) * AG + BN * 8;
    constexpr int NITER = NG / 512;

    extern __shared__ __align__(128) char smem[];
    const uint32_t sbase = smem_u32(smem);
    const int tid  = threadIdx.x;
    const int wid  = tid >> 5;
    const int lane = tid & 31;
    const int wm = wid & 3;
    const int wn = wid >> 2;
    const int m0 = blockIdx.y * AM;
    const int n0 = blockIdx.x * BN;

    const int gz = gridDim.z, bz = blockIdx.z;
    const int cbeg = (nchunk * bz) / gz;
    const int cend = (nchunk * (bz + 1)) / gz;
    C += (size_t)bz * part_stride;

    const char* baseAhi = (const char*)(Ahi + (size_t)m0 * ldA);
    const char* baseAlo = DUAL ? (const char*)(Alo + (size_t)m0 * ldA) : nullptr;
    const char* baseBhi = (const char*)(Bhi + (size_t)n0 * ldB);
    const size_t sA = (size_t)ldA * 2, sB = (size_t)ldB * 2;

    auto load_stage = [&](int c) {
        const uint32_t st = sbase + (uint32_t)(c % 3) * SS;
        const size_t kb = (size_t)c * (BKC * 2);
#pragma unroll
        for (int i = 0; i < NITER; i++) {
            const int idx = tid + i * 512;
            const char* gb;
            uint32_t regoff;
            int rr;
            if (idx < AG)                      { rr = idx;           gb = baseAhi; regoff = 0; }
            else if (DUAL && idx < 2 * AG)     { rr = idx - AG;      gb = baseAlo; regoff = A_B; }
            else                               { rr = idx - (DUAL ? 2 : 1) * AG;
                                                 gb = baseBhi; regoff = (DUAL ? 2u : 1u) * A_B; }
            const int r  = rr >> 3;
            const int cc = rr & 7;
            const size_t stride = (regoff == (DUAL ? 2u : 1u) * A_B && idx >= (DUAL ? 2 : 1) * AG) ? sB : sA;
            cp_async16(st + regoff + swz((uint32_t)(r * 128 + cc * 16)),
                       gb + kb + (size_t)r * stride + cc * 16);
        }
        cp_commit();
    };

    const uint32_t rL   = lane & 15;
    const uint32_t cAdd = lane >> 4;
    const uint32_t aRow0 = (uint32_t)(wm * (MT * 16)) + rL;
    const uint32_t bRow0 = (uint32_t)(wn * (NH * 16)) + rL;
    const uint32_t kOff0 = cAdd * 16u;

    float acc[MT][2 * NH][4];
#pragma unroll
    for (int i = 0; i < MT; i++)
#pragma unroll
        for (int j = 0; j < 2 * NH; j++)
#pragma unroll
            for (int k = 0; k < 4; k++) acc[i][j][k] = 0.0f;

    load_stage(cbeg);
    if (cbeg + 1 < cend) load_stage(cbeg + 1);

    for (int c = cbeg; c < cend; c++) {
        if (c + 1 < cend) cp_wait<1>(); else cp_wait<0>();
        __syncthreads();
        if (c + 2 < cend) load_stage(c + 2);

        const uint32_t st   = sbase + (uint32_t)(c % 3) * SS;
        const uint32_t tAhi = st;
        const uint32_t tAlo = st + A_B;
        const uint32_t tBhi = st + (DUAL ? 2u : 1u) * A_B;

#pragma unroll
        for (int ks = 0; ks < 4; ks++) {
            const uint32_t kb = kOff0 + (uint32_t)ks * 32u;
            uint32_t Ah[MT][4], Al[DUAL ? MT : 1][4], Bh[NH][4];
#pragma unroll
            for (int mt = 0; mt < MT; mt++) {
                const uint32_t off = (aRow0 + mt * 16u) * 128u + kb;
                ldsm4(Ah[mt], tAhi + swz(off));
                if (DUAL) ldsm4(Al[mt], tAlo + swz(off));
            }
#pragma unroll
            for (int nh = 0; nh < NH; nh++) {
                const uint32_t off = (bRow0 + nh * 16u) * 128u + kb;
                ldsm4(Bh[nh], tBhi + swz(off));
            }
#pragma unroll
            for (int mt = 0; mt < MT; mt++)
#pragma unroll
                for (int nh = 0; nh < NH; nh++) {
                    mma_f16(acc[mt][2 * nh + 0], Ah[mt], Bh[nh][0], Bh[nh][2]);
                    mma_f16(acc[mt][2 * nh + 1], Ah[mt], Bh[nh][1], Bh[nh][3]);
                    if (DUAL) {
                        mma_f16(acc[mt][2 * nh + 0], Al[mt], Bh[nh][0], Bh[nh][2]);
                        mma_f16(acc[mt][2 * nh + 1], Al[mt], Bh[nh][1], Bh[nh][3]);
                    }
                }
        }
    }

    // ---- epilogue ----
    const int trow  = lane >> 2;
    const int tcol2 = (lane & 3) * 2;
#pragma unroll
    for (int mt = 0; mt < MT; mt++) {
#pragma unroll
        for (int h = 0; h < 2; h++) {
            const int gr = m0 + wm * (MT * 16) + mt * 16 + h * 8 + trow;
#pragma unroll
            for (int nf = 0; nf < 2 * NH; nf++) {
                const int gc = n0 + wn * (NH * 16) + nf * 8 + tcol2;
                if constexpr (sizeof(OutT) == 2) {
                    __half2 v;
                    v.x = __float2half(acc[mt][nf][h * 2 + 0]);
                    v.y = __float2half(acc[mt][nf][h * 2 + 1]);
                    *reinterpret_cast<__half2*>(
                        reinterpret_cast<__half*>(C) + (size_t)gr * ldC + gc) = v;
                } else {
                    float2 v;
                    v.x = acc[mt][nf][h * 2 + 0];
                    v.y = acc[mt][nf][h * 2 + 1];
                    *reinterpret_cast<float2*>(
                        reinterpret_cast<float*>(C) + (size_t)gr * ldC + gc) = v;
                }
            }
        }
    }
}

// ------- reduce for H: Hh = half(relu(sum parts + b1)) over all MPAD rows -------
template <int NP>
__global__ void reduce_h_kernel(const float* __restrict__ part, size_t stride,
                                const float* __restrict__ bias,
                                __half* __restrict__ out)
{
    const int t = blockIdx.x * blockDim.x + threadIdx.x;
    if (t >= MPAD * (NHID / 4)) return;
    const int r = t / (NHID / 4);
    const int c = (t % (NHID / 4)) * 4;
    float4 s = *reinterpret_cast<const float4*>(bias + c);
#pragma unroll
    for (int p = 0; p < NP; p++) {
        const float4 v = *reinterpret_cast<const float4*>(part + p * stride + (size_t)r * NHID + c);
        s.x += v.x; s.y += v.y; s.z += v.z; s.w += v.w;
    }
    __half2 h0, h1;
    h0.x = __float2half(fmaxf(s.x, 0.0f));
    h0.y = __float2half(fmaxf(s.y, 0.0f));
    h1.x = __float2half(fmaxf(s.z, 0.0f));
    h1.y = __float2half(fmaxf(s.w, 0.0f));
    __half2* op = reinterpret_cast<__half2*>(out + (size_t)r * NHID + c);
    op[0] = h0; op[1] = h1;
}

// ------- final reduce: out = sum parts + bias -------
template <int NP>
__global__ void reduce_kernel(const float* __restrict__ part, size_t stride,
                              const float* __restrict__ bias,
                              float* __restrict__ out, int rows, int cols)
{
    const int t = blockIdx.x * blockDim.x + threadIdx.x;
    if (t >= rows * (cols / 4)) return;
    const int r = t / (cols / 4);
    const int c = (t % (cols / 4)) * 4;
    float4 s = *reinterpret_cast<const float4*>(bias + c);
#pragma unroll
    for (int p = 0; p < NP; p++) {
        const float4 v = *reinterpret_cast<const float4*>(part + p * stride + (size_t)r * cols + c);
        s.x += v.x; s.y += v.y; s.z += v.z; s.w += v.w;
    }
    *reinterpret_cast<float4*>(out + (size_t)r * cols + c) = s;
}

// ---------------- adj round: fp32 [NROWS,NROWS] -> fp16 [MPAD,KPAD] ----------------
__global__ void round_adj_kernel(const float* __restrict__ adj,
                                 __half* __restrict__ hi)
{
    const long long t = (long long)blockIdx.x * blockDim.x + threadIdx.x;
    const long long total = (long long)MPAD * (KPAD / 4);
    if (t >= total) return;
    const int c4 = (int)(t % (KPAD / 4));
    const int r  = (int)(t / (KPAD / 4));
    const int k  = c4 * 4;
    float4 v = make_float4(0.f, 0.f, 0.f, 0.f);
    if (r < NROWS && k < NROWS)   // NROWS % 4 == 0, so k < NROWS => k+3 < NROWS
        v = *reinterpret_cast<const float4*>(adj + (size_t)r * NROWS + k);
    __half2 H01, H23;
    H01.x = __float2half(v.x); H01.y = __float2half(v.y);
    H23.x = __float2half(v.z); H23.y = __float2half(v.w);
    __half2* hp = reinterpret_cast<__half2*>(hi + (size_t)r * KPAD + k);
    hp[0] = H01; hp[1] = H23;
}

// ---------------- x round: fp32 [NROWS,NFEAT] -> fp16 [KPAD,NFEAT] ----------------
__global__ void round_x_kernel(const float* __restrict__ x,
                               __half* __restrict__ xh)
{
    const int t = blockIdx.x * blockDim.x + threadIdx.x;
    if (t >= KPAD * (NFEAT / 4)) return;
    const int r = t / (NFEAT / 4);
    const int c = (t % (NFEAT / 4)) * 4;
    float4 v = make_float4(0.f, 0.f, 0.f, 0.f);
    if (r < NROWS)
        v = *reinterpret_cast<const float4*>(x + (size_t)r * NFEAT + c);
    __half2 H01, H23;
    H01.x = __float2half(v.x); H01.y = __float2half(v.y);
    H23.x = __float2half(v.z); H23.y = __float2half(v.w);
    __half2* hp = reinterpret_cast<__half2*>(xh + (size_t)r * NFEAT + c);
    hp[0] = H01; hp[1] = H23;
}

// ---- generic weight transpose+split: fp32 [R,C] -> fp16 hi/lo [C,R] ----
__global__ void wt_split_kernel(const float* __restrict__ W, int R, int C,
                                __half* __restrict__ hi,
                                __half* __restrict__ lo)
{
    __shared__ float tile[32][33];
    const int tx = threadIdx.x, ty = threadIdx.y;
    const int c0 = blockIdx.x * 32;   // C dim (output rows)
    const int k0 = blockIdx.y * 32;   // R dim (output cols)
#pragma unroll
    for (int i = 0; i < 4; i++) {
        const int k = k0 + ty + i * 8;
        tile[ty + i * 8][tx] = W[(size_t)k * C + (c0 + tx)];
    }
    __syncthreads();
#pragma unroll
    for (int i = 0; i < 4; i++) {
        const int c = c0 + ty + i * 8;
        const float v = tile[tx][ty + i * 8];
        const __half h = __float2half(v);
        hi[(size_t)c * R + k0 + tx] = h;
        lo[(size_t)c * R + k0 + tx] = __float2half(v - __half2float(h));
    }
}

// ---------------- launcher ----------------
extern "C" void kernel_launch(void* const* d_in, const int* in_sizes, int n_in,
                              void* d_out, int out_size)
{
    const float* x   = (const float*)d_in[0];
    const float* adj = (const float*)d_in[1];
    const float* W1  = (const float*)d_in[2];
    const float* b1  = (const float*)d_in[3];
    const float* W2  = (const float*)d_in[4];
    const float* b2  = (const float*)d_in[5];
    float* out = (float*)d_out;

    float* part;
    __half *Ah, *xh, *W1thi, *W1tlo, *T1t, *Hh, *W2thi, *W2tlo, *T2t;
    cudaGetSymbolAddress((void**)&part, g_part);
    cudaGetSymbolAddress((void**)&Ah,   g_adj_h);
    cudaGetSymbolAddress((void**)&xh,   g_xh);
    cudaGetSymbolAddress((void**)&W1thi, g_W1t_hi);
    cudaGetSymbolAddress((void**)&W1tlo, g_W1t_lo);
    cudaGetSymbolAddress((void**)&T1t,  g_T1t);
    cudaGetSymbolAddress((void**)&Hh,   g_Hh);
    cudaGetSymbolAddress((void**)&W2thi, g_W2t_hi);
    cudaGetSymbolAddress((void**)&W2tlo, g_W2t_lo);
    cudaGetSymbolAddress((void**)&T2t,  g_T2t);

    cudaFuncSetAttribute((const void*)tc_gemm<128, 128, true, __half>,
                         cudaFuncAttributeMaxDynamicSharedMemorySize, TC_SMEM);
    cudaFuncSetAttribute((const void*)tc_gemm<256, 128, false, float>,
                         cudaFuncAttributeMaxDynamicSharedMemorySize, TC_SMEM);
    cudaFuncSetAttribute((const void*)tc_gemm<128, 256, false, float>,
                         cudaFuncAttributeMaxDynamicSharedMemorySize, TC_SMEM);

    // adj -> fp16 [MPAD, KPAD]
    {
        const long long total = (long long)MPAD * (KPAD / 4);
        round_adj_kernel<<<(unsigned)((total + 255) / 256), 256>>>(adj, Ah);
    }
    // x -> fp16 [KPAD, NFEAT] (rows >= NROWS zero)
    round_x_kernel<<<(KPAD * (NFEAT / 4) + 255) / 256, 256>>>(x, xh);
    // W1^T hi/lo [NHID, NFEAT]
    wt_split_kernel<<<dim3(NHID / 32, NFEAT / 32), dim3(32, 8)>>>(W1, NFEAT, NHID, W1thi, W1tlo);
    // T1t = half((W1t_hi+W1t_lo) @ xh^T) [NHID, KPAD]; K = NFEAT (8 chunks)
    tc_gemm<128, 128, true, __half><<<dim3(KPAD / 128, NHID / 128, 1), 512, TC_SMEM>>>(
        W1thi, W1tlo, xh, T1t, NFEAT, NFEAT, KPAD, NFEAT / BKC, 0);
    // gemm2 partials: part[z] = Ah @ T1t^T  (256x128 tiles, K-split Z2)
    tc_gemm<256, 128, false, float><<<dim3(1, MPAD / 256, Z2), 512, TC_SMEM>>>(
        Ah, nullptr, T1t, part, KPAD, KPAD, NHID, NCHUNK, (size_t)MPAD * NHID);
    // Hh = half(relu(sum parts + b1)) [MPAD, NHID]
    reduce_h_kernel<Z2><<<(MPAD * (NHID / 4) + 255) / 256, 256>>>(
        part, (size_t)MPAD * NHID, b1, Hh);
    // W2^T hi/lo [NFEAT, NHID]
    wt_split_kernel<<<dim3(NFEAT / 32, NHID / 32), dim3(32, 8)>>>(W2, NHID, NFEAT, W2thi, W2tlo);
    // T2t = half((W2t_hi+W2t_lo) @ Hh^T) [NFEAT, KPAD]; K = NHID (2 chunks)
    tc_gemm<128, 128, true, __half><<<dim3(KPAD / 128, NFEAT / 128, 1), 512, TC_SMEM>>>(
        W2thi, W2tlo, Hh, T2t, NHID, NHID, KPAD, NHID / BKC, 0);
    // gemm4 partials: part[z] = Ah @ T2t^T  (128x256 tiles, K-split Z4)
    tc_gemm<128, 256, false, float><<<dim3(NFEAT / 256, KPAD / 128, Z4), 512, TC_SMEM>>>(
        Ah, nullptr, T2t, part, KPAD, KPAD, NFEAT, NCHUNK, (size_t)MPAD * NFEAT);
    // out = sum parts + b2
    reduce_kernel<Z4><<<(NROWS * (NFEAT / 4) + 255) / 256, 256>>>(
        part, (size_t)MPAD * NFEAT, b2, out, NROWS, NFEAT);
}